// round 4
// baseline (speedup 1.0000x reference)
#include <cuda_runtime.h>
#include <cuda_bf16.h>
#include <math.h>
#include <float.h>

#define N_NODES 50000
#define N_EDGES 1600000
#define N_MSG   (N_EDGES + N_NODES)
#define F_IN    3
#define C_OUT   40

// ---------------- scratch (static device globals; no allocation) ----------------
// 256B-aligned so vectorized float4 access is always legal.
__device__ __align__(256) float g_agg[N_NODES * 64];     // segment-max result
__device__ __align__(256) float g_g1 [N_NODES * 128];    // after W3+relu
__device__ __align__(256) float g_g2 [N_NODES * 1024];   // after W4+relu
__device__ __align__(256) float g_g3 [N_NODES * 64];     // after W5 (no relu)

// ---------------- helpers ----------------
__device__ __forceinline__ void atomicMaxFloat(float* addr, float v) {
    // Exact float max via monotone int/uint reinterpretation.
    if (v >= 0.0f) {
        atomicMax((int*)addr, __float_as_int(v));
    } else {
        atomicMin((unsigned int*)addr, __float_as_uint(v));
    }
}

// ---------------- kernel 0: init agg to -FLT_MAX ----------------
__global__ void k_init_agg() {
    int i = blockIdx.x * blockDim.x + threadIdx.x;
    int total = N_NODES * 64;
    if (i < total) g_agg[i] = -FLT_MAX;
}

// ---------------- kernel 1: fused edge MLP + atomic segment-max ----------------
// msg_in = [x_j(3), pos_j - pos_i(3)];  h1 = relu(msg_in @ W1 + b1);  h = h1 @ W2 + b2
// agg[dst] = max(agg[dst], h)   (elementwise, 64 channels)
__global__ __launch_bounds__(256) void k_edge(
    const float* __restrict__ x,          // [N,3]
    const float* __restrict__ pos,        // [N,3]
    const int*   __restrict__ ei,         // [2,E]  (int32! JAX x64 is off)
    const float* __restrict__ W1,         // [6,64]
    const float* __restrict__ b1,         // [64]
    const float* __restrict__ W2,         // [64,64]
    const float* __restrict__ b2)         // [64]
{
    __shared__ float sW1[6 * 64];
    __shared__ float sb1[64];
    __shared__ float sW2[64 * 64];
    __shared__ float sb2[64];

    for (int i = threadIdx.x; i < 6 * 64; i += blockDim.x) sW1[i] = W1[i];
    for (int i = threadIdx.x; i < 64; i += blockDim.x) { sb1[i] = b1[i]; sb2[i] = b2[i]; }
    for (int i = threadIdx.x; i < 64 * 64; i += blockDim.x) sW2[i] = W2[i];
    __syncthreads();

    int m = blockIdx.x * blockDim.x + threadIdx.x;
    if (m >= N_MSG) return;

    int src, dst;
    if (m < N_EDGES) {
        src = ei[m];
        dst = ei[N_EDGES + m];
    } else {
        src = dst = m - N_EDGES;   // self-loop
    }

    float in[6];
    in[0] = x[src * 3 + 0];
    in[1] = x[src * 3 + 1];
    in[2] = x[src * 3 + 2];
    in[3] = pos[src * 3 + 0] - pos[dst * 3 + 0];
    in[4] = pos[src * 3 + 1] - pos[dst * 3 + 1];
    in[5] = pos[src * 3 + 2] - pos[dst * 3 + 2];

    float acc[64];
    #pragma unroll
    for (int o = 0; o < 64; o++) acc[o] = sb2[o];

    // per k: recompute h1[k], rank-1 update into acc
    for (int k = 0; k < 64; k++) {
        float h = sb1[k];
        #pragma unroll
        for (int i = 0; i < 6; i++) h = fmaf(in[i], sW1[i * 64 + k], h);
        h = fmaxf(h, 0.0f);
        const float4* wrow = (const float4*)(sW2 + k * 64);
        #pragma unroll
        for (int o4 = 0; o4 < 16; o4++) {
            float4 w = wrow[o4];
            acc[o4 * 4 + 0] = fmaf(h, w.x, acc[o4 * 4 + 0]);
            acc[o4 * 4 + 1] = fmaf(h, w.y, acc[o4 * 4 + 1]);
            acc[o4 * 4 + 2] = fmaf(h, w.z, acc[o4 * 4 + 2]);
            acc[o4 * 4 + 3] = fmaf(h, w.w, acc[o4 * 4 + 3]);
        }
    }

    float* dstp = g_agg + (size_t)dst * 64;
    #pragma unroll
    for (int o = 0; o < 64; o++) atomicMaxFloat(dstp + o, acc[o]);
}

// ---------------- generic register-tiled fp32 GEMM: C = act(A @ W + b) ----------------
// Tile: 128 rows x 64 cols, BLK_K=32, 256 threads, each thread 8x4 accumulators.
template<int K_TOT, int NOUT, bool RELU_OUT>
__global__ __launch_bounds__(256) void k_mlp_gemm(
    const float* __restrict__ A,   // [nrows, K_TOT]
    const float* __restrict__ W,   // [K_TOT, NOUT]
    const float* __restrict__ b,   // [NOUT]
    float* __restrict__ C,         // [nrows, NOUT]
    int nrows)
{
    __shared__ float As[32][129];   // k-major, padded
    __shared__ float Bs[32][64];

    const int tid = threadIdx.x;
    const int n0 = blockIdx.x * 128;
    const int o0 = blockIdx.y * 64;

    const int ot = tid & 15;        // 16 out-tiles of 4
    const int nt = tid >> 4;        // 16 node-tiles of 8

    float acc[8][4];
    #pragma unroll
    for (int j = 0; j < 8; j++)
        #pragma unroll
        for (int q = 0; q < 4; q++) acc[j][q] = 0.0f;

    const int kk = tid & 31;        // for A load
    const int nr = tid >> 5;        // 0..7
    const int oo = tid & 63;        // for B load
    const int kb = tid >> 6;        // 0..3

    for (int k0 = 0; k0 < K_TOT; k0 += 32) {
        // load A tile: As[kk][n] = A[n0+n][k0+kk]
        #pragma unroll
        for (int jj = 0; jj < 16; jj++) {
            int n = nr * 16 + jj;
            int row = n0 + n;
            float v = 0.0f;
            if (row < nrows) v = A[(size_t)row * K_TOT + k0 + kk];
            As[kk][n] = v;
        }
        // load B tile: Bs[k][oo] = W[(k0+k)*NOUT + o0+oo]
        #pragma unroll
        for (int jj = 0; jj < 8; jj++) {
            int k = kb * 8 + jj;
            Bs[k][oo] = W[(size_t)(k0 + k) * NOUT + o0 + oo];
        }
        __syncthreads();

        #pragma unroll
        for (int k = 0; k < 32; k++) {
            float4 wv = *(const float4*)&Bs[k][ot * 4];
            float av[8];
            #pragma unroll
            for (int j = 0; j < 8; j++) av[j] = As[k][nt * 8 + j];
            #pragma unroll
            for (int j = 0; j < 8; j++) {
                acc[j][0] = fmaf(av[j], wv.x, acc[j][0]);
                acc[j][1] = fmaf(av[j], wv.y, acc[j][1]);
                acc[j][2] = fmaf(av[j], wv.z, acc[j][2]);
                acc[j][3] = fmaf(av[j], wv.w, acc[j][3]);
            }
        }
        __syncthreads();
    }

    float bias0 = b[o0 + ot * 4 + 0];
    float bias1 = b[o0 + ot * 4 + 1];
    float bias2 = b[o0 + ot * 4 + 2];
    float bias3 = b[o0 + ot * 4 + 3];
    #pragma unroll
    for (int j = 0; j < 8; j++) {
        int row = n0 + nt * 8 + j;
        if (row >= nrows) continue;
        float4 v;
        v.x = acc[j][0] + bias0;
        v.y = acc[j][1] + bias1;
        v.z = acc[j][2] + bias2;
        v.w = acc[j][3] + bias3;
        if (RELU_OUT) {
            v.x = fmaxf(v.x, 0.0f); v.y = fmaxf(v.y, 0.0f);
            v.z = fmaxf(v.z, 0.0f); v.w = fmaxf(v.w, 0.0f);
        }
        *(float4*)&C[(size_t)row * NOUT + o0 + ot * 4] = v;
    }
}

// ---------------- kernel: relu(g3) @ Wf + bf, then log_softmax ----------------
// one warp per node; lane handles out=lane and out=lane+32 (lanes 0..7)
__global__ __launch_bounds__(256) void k_fc_softmax(
    const float* __restrict__ Wf,  // [64,40]
    const float* __restrict__ bf,  // [40]
    float* __restrict__ out)       // [N,40]
{
    __shared__ float sWf[64 * 40];
    __shared__ float sbf[40];
    for (int i = threadIdx.x; i < 64 * 40; i += blockDim.x) sWf[i] = Wf[i];
    for (int i = threadIdx.x; i < 40; i += blockDim.x) sbf[i] = bf[i];
    __syncthreads();

    int warp = threadIdx.x >> 5;
    int lane = threadIdx.x & 31;
    int node = blockIdx.x * 8 + warp;
    if (node >= N_NODES) return;

    const float* g = g_g3 + (size_t)node * 64;
    float v0 = sbf[lane];
    float v1 = (lane < 8) ? sbf[lane + 32] : -FLT_MAX;

    for (int k = 0; k < 64; k++) {
        float a = fmaxf(g[k], 0.0f);
        v0 = fmaf(a, sWf[k * 40 + lane], v0);
        if (lane < 8) v1 = fmaf(a, sWf[k * 40 + lane + 32], v1);
    }

    // warp-reduce max over 40 values
    float m = fmaxf(v0, v1);
    #pragma unroll
    for (int off = 16; off > 0; off >>= 1)
        m = fmaxf(m, __shfl_xor_sync(0xFFFFFFFFu, m, off));

    float s = __expf(v0 - m) + ((lane < 8) ? __expf(v1 - m) : 0.0f);
    #pragma unroll
    for (int off = 16; off > 0; off >>= 1)
        s += __shfl_xor_sync(0xFFFFFFFFu, s, off);

    float ls = __logf(s);
    float* op = out + (size_t)node * 40;
    op[lane] = v0 - m - ls;
    if (lane < 8) op[lane + 32] = v1 - m - ls;
}

// ---------------- launcher ----------------
extern "C" void kernel_launch(void* const* d_in, const int* in_sizes, int n_in,
                              void* d_out, int out_size) {
    const float* x   = (const float*)d_in[0];
    const float* pos = (const float*)d_in[1];
    const int*   ei  = (const int*)d_in[2];      // int32 (JAX default x64 disabled)
    const float* W1 = (const float*)d_in[3];
    const float* b1 = (const float*)d_in[4];
    const float* W2 = (const float*)d_in[5];
    const float* b2 = (const float*)d_in[6];
    const float* W3 = (const float*)d_in[7];
    const float* b3 = (const float*)d_in[8];
    const float* W4 = (const float*)d_in[9];
    const float* b4 = (const float*)d_in[10];
    const float* W5 = (const float*)d_in[11];
    const float* b5 = (const float*)d_in[12];
    const float* Wf = (const float*)d_in[13];
    const float* bf = (const float*)d_in[14];
    float* out = (float*)d_out;

    k_init_agg<<<(N_NODES * 64 + 255) / 256, 256>>>();
    k_edge<<<(N_MSG + 255) / 256, 256>>>(x, pos, ei, W1, b1, W2, b2);

    float* agg = nullptr; float* g1 = nullptr; float* g2 = nullptr; float* g3 = nullptr;
    cudaGetSymbolAddress((void**)&agg, g_agg);
    cudaGetSymbolAddress((void**)&g1, g_g1);
    cudaGetSymbolAddress((void**)&g2, g_g2);
    cudaGetSymbolAddress((void**)&g3, g_g3);

    dim3 grd3((N_NODES + 127) / 128, 128 / 64);
    k_mlp_gemm<64, 128, true><<<grd3, 256>>>(agg, W3, b3, g1, N_NODES);

    dim3 grd4((N_NODES + 127) / 128, 1024 / 64);
    k_mlp_gemm<128, 1024, true><<<grd4, 256>>>(g1, W4, b4, g2, N_NODES);

    dim3 grd5((N_NODES + 127) / 128, 64 / 64);
    k_mlp_gemm<1024, 64, false><<<grd5, 256>>>(g2, W5, b5, g3, N_NODES);

    k_fc_softmax<<<(N_NODES + 7) / 8, 256>>>(Wf, bf, out);
}